// round 5
// baseline (speedup 1.0000x reference)
#include <cuda_runtime.h>

// 2-layer LSTM (B=2048, T=512, I=1, H=50) + FC(50->1).
// 128 persistent CTAs x 16 batch. 672 threads = 3 groups of 224
// (thread = (grp, b in [0,4), k in [0,56))). Each group owns ONE matvec:
//   g0: W_hh0 . h1  -> L1 gates -> h1[u]
//   g1: W_ih1 . h1  -> (+ g2 partial) -> L2 gates -> h2[u-1]
//   g2: W_hh1 . h2  -> partial sums to SMEM exchange
// Layer-skewed (L1 at t=u, L2 at t=u-1). fma.rn.f32x2 on LDS.128.
// Sync: named bar(448) g1<->g2 + one __syncthreads per step.

#define HID   50
#define KP    56
#define BT    16
#define WS    52          // weight row stride (floats)
#define HS    52          // h row stride
#define SXS   513         // x row stride (odd)
#define GRPT  224
#define NTH   672
#define SEQL  512
#define NBATCH 2048
#define HBUF  (BT * HS)
#define GS2   (KP * WS / 4)   // 728 ulonglong2 between gate blocks
#define ESTR  20               // exchange row stride (floats), conflict-free

__device__ __forceinline__ float ftanh(float v) {
    float y;
    asm("tanh.approx.f32 %0, %1;" : "=f"(y) : "f"(v));
    return y;
}
__device__ __forceinline__ float fsigm(float v) {
    return fmaf(0.5f, ftanh(0.5f * v), 0.5f);
}
__device__ __forceinline__ void fma2(unsigned long long& d,
                                     unsigned long long a, unsigned long long b) {
    asm("fma.rn.f32x2 %0, %1, %2, %0;" : "+l"(d) : "l"(a), "l"(b));
}
__device__ __forceinline__ float hsum2(unsigned long long d) {
    float lo, hi;
    asm("mov.b64 {%0, %1}, %2;" : "=f"(lo), "=f"(hi) : "l"(d));
    return lo + hi;
}
#define BAR12() asm volatile("bar.sync 1, 448;" ::: "memory")

__global__ __launch_bounds__(NTH, 1)
void lstm2_kernel(const float* __restrict__ x,
                  const float* __restrict__ W_ih0, const float* __restrict__ W_hh0,
                  const float* __restrict__ b_ih0, const float* __restrict__ b_hh0,
                  const float* __restrict__ W_ih1, const float* __restrict__ W_hh1,
                  const float* __restrict__ b_ih1, const float* __restrict__ b_hh1,
                  const float* __restrict__ fc_W, const float* __restrict__ fc_b,
                  float* __restrict__ out)
{
    extern __shared__ float sm[];
    float* sW0  = sm;                    // W_hh0  [4*KP][WS]
    float* sWi1 = sW0  + 4 * KP * WS;
    float* sWh1 = sWi1 + 4 * KP * WS;
    float* sX   = sWh1 + 4 * KP * WS;    // [BT][SXS]
    float* h1s  = sX   + BT * SXS;       // 2 bufs [BT][HS]
    float* h2s  = h1s  + 2 * HBUF;       // 2 bufs
    float* exch = h2s  + 2 * HBUF;       // [GRPT][ESTR]

    const int tid = threadIdx.x;
    const int grp = tid / GRPT;          // 0,1,2
    const int r   = tid - grp * GRPT;
    const int b   = r & 3;
    const int k   = r >> 2;              // 0..55 (50..55 dummy)
    const bool act = (k < HID);
    const int bg  = blockIdx.x * BT;

    // ---- prologue: stage weights (zero-padded), x tile, zero h ----
    for (int i = tid; i < 4 * KP * WS; i += NTH) {
        int row = i / WS, c = i - row * WS;
        int g = row / KP, kr = row - g * KP;
        bool in = (kr < HID) && (c < HID);
        int src = (g * HID + kr) * HID + c;
        sW0 [i] = in ? W_hh0[src] : 0.0f;
        sWi1[i] = in ? W_ih1[src] : 0.0f;
        sWh1[i] = in ? W_hh1[src] : 0.0f;
    }
    for (int i = tid; i < BT * SEQL; i += NTH) {
        int bl = i >> 9;
        int t  = i & (SEQL - 1);
        sX[bl * SXS + t] = x[(size_t)(bg + bl) * SEQL + t];
    }
    for (int i = tid; i < 4 * HBUF; i += NTH) h1s[i] = 0.0f;

    const int ksafe = act ? k : 0;
    float wi0[4], bs0[4], bs1[4];
    #pragma unroll
    for (int g = 0; g < 4; g++) {
        int row = g * HID + ksafe;
        wi0[g] = W_ih0[row];
        bs0[g] = b_ih0[row] + b_hh0[row];
        bs1[g] = b_ih1[row] + b_hh1[row];
    }
    float c1[4] = {0, 0, 0, 0};          // live in g0 threads
    float c2[4] = {0, 0, 0, 0};          // live in g1 threads
    __syncthreads();

    const float* wsel = (grp == 0) ? sW0 : (grp == 1) ? sWi1 : sWh1;
    const ulonglong2* wk = (const ulonglong2*)(wsel + k * WS);

    // ---- peel u=0: L1 only (h1[-1]=0) ----
    if (grp == 0) {
        float* h1w = h1s;                // buf 0
        #pragma unroll
        for (int bb = 0; bb < 4; bb++) {
            float xt = sX[(b + 4 * bb) * SXS];
            float i1 = fsigm(fmaf(xt, wi0[0], bs0[0]));
            float g1 = ftanh(fmaf(xt, wi0[2], bs0[2]));
            float o1 = fsigm(fmaf(xt, wi0[3], bs0[3]));
            c1[bb] = i1 * g1;
            if (act) h1w[(b + 4 * bb) * HS + k] = o1 * ftanh(c1[bb]);
        }
    }
    __syncthreads();

    // ---- main loop: u=1..512.  L1(t=u) [u<512], L2(t=u-1) ----
    for (int u = 1; u <= SEQL; u++) {
        // h source: g0,g1 read h1[u-1]; g2 reads h2[u-2]
        const float* hr = (grp == 2) ? (h2s + (u & 1) * HBUF)
                                     : (h1s + ((u + 1) & 1) * HBUF);
        const bool domv = (grp != 0) || (u < SEQL);

        unsigned long long acc[4][4];
        #pragma unroll
        for (int g = 0; g < 4; g++)
            #pragma unroll
            for (int bb = 0; bb < 4; bb++) acc[g][bb] = 0ULL;

        if (domv) {
            #pragma unroll
            for (int j = 0; j < 13; j++) {
                ulonglong2 hv[4];
                #pragma unroll
                for (int bb = 0; bb < 4; bb++)
                    hv[bb] = ((const ulonglong2*)(hr + (b + 4 * bb) * HS))[j];
                #pragma unroll
                for (int g = 0; g < 4; g++) {
                    ulonglong2 w = wk[j + g * GS2];
                    #pragma unroll
                    for (int bb = 0; bb < 4; bb++) {
                        fma2(acc[g][bb], w.x, hv[bb].x);
                        fma2(acc[g][bb], w.y, hv[bb].y);
                    }
                }
            }
        }

        if (grp == 0) {
            if (u < SEQL) {
                float* h1w = h1s + (u & 1) * HBUF;
                #pragma unroll
                for (int bb = 0; bb < 4; bb++) {
                    float xt = sX[(b + 4 * bb) * SXS + u];
                    float g0 = hsum2(acc[0][bb]) + fmaf(xt, wi0[0], bs0[0]);
                    float g1 = hsum2(acc[1][bb]) + fmaf(xt, wi0[1], bs0[1]);
                    float g2 = hsum2(acc[2][bb]) + fmaf(xt, wi0[2], bs0[2]);
                    float g3 = hsum2(acc[3][bb]) + fmaf(xt, wi0[3], bs0[3]);
                    float i1 = fsigm(g0), f1 = fsigm(g1);
                    float gg1 = ftanh(g2), o1 = fsigm(g3);
                    c1[bb] = fmaf(f1, c1[bb], i1 * gg1);
                    if (act) h1w[(b + 4 * bb) * HS + k] = o1 * ftanh(c1[bb]);
                }
            }
        } else if (grp == 2) {
            // export partials (W_hh1 . h2) for g1
            float* ex = exch + r * ESTR;
            #pragma unroll
            for (int bb = 0; bb < 4; bb++) {
                float4 p;
                p.x = hsum2(acc[0][bb]);
                p.y = hsum2(acc[1][bb]);
                p.z = hsum2(acc[2][bb]);
                p.w = hsum2(acc[3][bb]);
                *(float4*)(ex + bb * 4) = p;
            }
            BAR12();
        } else { // grp == 1
            float s0[4], s1[4], s2[4], s3[4];
            #pragma unroll
            for (int bb = 0; bb < 4; bb++) {
                s0[bb] = hsum2(acc[0][bb]);
                s1[bb] = hsum2(acc[1][bb]);
                s2[bb] = hsum2(acc[2][bb]);
                s3[bb] = hsum2(acc[3][bb]);
            }
            BAR12();
            float* h2w = h2s + ((u + 1) & 1) * HBUF;
            const float* ex = exch + r * ESTR;
            #pragma unroll
            for (int bb = 0; bb < 4; bb++) {
                float4 p = *(const float4*)(ex + bb * 4);
                float G0 = s0[bb] + p.x + bs1[0];
                float G1 = s1[bb] + p.y + bs1[1];
                float G2 = s2[bb] + p.z + bs1[2];
                float G3 = s3[bb] + p.w + bs1[3];
                float i2 = fsigm(G0), f2 = fsigm(G1);
                float gg2 = ftanh(G2), o2 = fsigm(G3);
                c2[bb] = fmaf(f2, c2[bb], i2 * gg2);
                if (act) h2w[(b + 4 * bb) * HS + k] = o2 * ftanh(c2[bb]);
            }
        }
        __syncthreads();
    }

    // ---- FC epilogue: h2[511] is in buf (512+1)&1 = buf 1 ----
    if (grp == 0 && k == 0) {
        const float* h2f = h2s + HBUF;
        float fb = fc_b[0];
        #pragma unroll
        for (int bb = 0; bb < 4; bb++) {
            float acc = fb;
            const float* hrow = h2f + (b + 4 * bb) * HS;
            #pragma unroll
            for (int kk = 0; kk < HID; kk++)
                acc = fmaf(hrow[kk], fc_W[kk], acc);
            out[bg + b + 4 * bb] = acc;
        }
    }
}

extern "C" void kernel_launch(void* const* d_in, const int* in_sizes, int n_in,
                              void* d_out, int out_size)
{
    const float* x     = (const float*)d_in[0];
    const float* W_ih0 = (const float*)d_in[1];
    const float* W_hh0 = (const float*)d_in[2];
    const float* b_ih0 = (const float*)d_in[3];
    const float* b_hh0 = (const float*)d_in[4];
    const float* W_ih1 = (const float*)d_in[5];
    const float* W_hh1 = (const float*)d_in[6];
    const float* b_ih1 = (const float*)d_in[7];
    const float* b_hh1 = (const float*)d_in[8];
    const float* fc_W  = (const float*)d_in[9];
    const float* fc_b  = (const float*)d_in[10];
    float* out = (float*)d_out;

    const int smem_bytes = (3 * 4 * KP * WS + BT * SXS + 4 * HBUF + GRPT * ESTR)
                           * (int)sizeof(float);
    cudaFuncSetAttribute(lstm2_kernel, cudaFuncAttributeMaxDynamicSharedMemorySize, smem_bytes);
    lstm2_kernel<<<NBATCH / BT, NTH, smem_bytes>>>(
        x, W_ih0, W_hh0, b_ih0, b_hh0,
        W_ih1, W_hh1, b_ih1, b_hh1, fc_W, fc_b, out);
}